// round 1
// baseline (speedup 1.0000x reference)
#include <cuda_runtime.h>

typedef unsigned long long u64;

// ---- packed f32x2 helpers (sm_103a) ----
__device__ __forceinline__ u64 pack2(float lo, float hi) {
    u64 d;
    asm("mov.b64 %0, {%1, %2};" : "=l"(d) : "r"(__float_as_uint(lo)), "r"(__float_as_uint(hi)));
    return d;
}
__device__ __forceinline__ void unpack2(u64 v, float& lo, float& hi) {
    unsigned a, b;
    asm("mov.b64 {%0, %1}, %2;" : "=r"(a), "=r"(b) : "l"(v));
    lo = __uint_as_float(a); hi = __uint_as_float(b);
}
__device__ __forceinline__ u64 fma2(u64 a, u64 b, u64 c) {
    u64 d;
    asm("fma.rn.f32x2 %0, %1, %2, %3;" : "=l"(d) : "l"(a), "l"(b), "l"(c));
    return d;
}
__device__ __forceinline__ u64 mul2(u64 a, u64 b) {
    u64 d;
    asm("mul.rn.f32x2 %0, %1, %2;" : "=l"(d) : "l"(a), "l"(b));
    return d;
}
__device__ __forceinline__ u64 add2(u64 a, u64 b) {
    u64 d;
    asm("add.rn.f32x2 %0, %1, %2;" : "=l"(d) : "l"(a), "l"(b));
    return d;
}
__device__ __forceinline__ u64 relu2(u64 v) {
    float lo, hi; unpack2(v, lo, hi);
    lo = fmaxf(lo, 0.0f); hi = fmaxf(hi, 0.0f);
    return pack2(lo, hi);
}

// ---- problem constants ----
constexpr int W_DIM = 4096;
constexpr int C_DIM = 64;
constexpr int L_SEG = 256;            // outputs per warp
constexpr int T_STEPS = 320;          // 305 needed (L+49), padded to mult of 32
constexpr int SEGS = W_DIM / L_SEG;   // 16
constexpr int BH = 16 * 21;           // 336 (B*H rows)

// Cross-correlation, zero pad. pad_lo: d=1 -> 3, d=2 -> 7, d=4 -> 14.
// y1[w] = relu(sum_k x [w- 3+  k] * w1[k])
// y2[w] = relu(sum_k y1[w- 7+ 2k] * w2[k])   (y1 := 0 outside [0,W))
// y3[w] = relu(sum_k y2[w-14+ 4k] * w3[k])   (y2 := 0 outside [0,W))
//
// Streaming pipeline (per warp lane = 2 channels packed f32x2):
//   step i loads x[t], t = s0-24+i; computes y1[t-4], y2[t-11], y3[t-25].
//   Ring sizes 8/16/32 all divide 32 => static indices in a 32x unrolled body.

template<bool BOUNDARY>
__global__ void __launch_bounds__(128)
conv_stack_kernel(const float* __restrict__ x,
                  const float* __restrict__ w1,
                  const float* __restrict__ w2,
                  const float* __restrict__ w3,
                  float* __restrict__ out)
{
    const int warp = blockIdx.x * 4 + (threadIdx.x >> 5);
    const int lane = threadIdx.x & 31;

    int bh, seg;
    if (BOUNDARY) { bh = warp >> 1;          seg = (warp & 1) ? (SEGS - 1) : 0; }
    else          { bh = warp / (SEGS - 2);  seg = 1 + (warp % (SEGS - 2)); }

    const int s0 = seg * L_SEG;
    const int t0 = s0 - 24;

    // per-channel-pair weights (8 taps each), contiguous float2 at k*64 + 2*lane
    u64 w1r[8], w2r[8], w3r[8];
    #pragma unroll
    for (int k = 0; k < 8; ++k) {
        w1r[k] = *(const u64*)(w1 + k * C_DIM + 2 * lane);
        w2r[k] = *(const u64*)(w2 + k * C_DIM + 2 * lane);
        w3r[k] = *(const u64*)(w3 + k * C_DIM + 2 * lane);
    }

    const float* ld_base = x   + ((long long)bh * W_DIM + t0) * C_DIM + 2 * lane;
    float*       st_base = out + ((long long)bh * W_DIM + (s0 - 49)) * C_DIM + 2 * lane;

    u64 xr[8], y1r[16], y2r[32];
    #pragma unroll
    for (int j = 0; j < 8;  ++j) xr[j]  = 0ull;
    #pragma unroll
    for (int j = 0; j < 16; ++j) y1r[j] = 0ull;
    #pragma unroll
    for (int j = 0; j < 32; ++j) y2r[j] = 0ull;

    for (int ib = 0; ib < T_STEPS; ib += 32) {
        #pragma unroll
        for (int u = 0; u < 32; ++u) {
            const int i = ib + u;

            // ---- load x[t], t = t0 + i (interior: always in-bounds, incl. 15-step overrun)
            u64 xv;
            if (BOUNDARY) {
                const int t = t0 + i;
                xv = (t >= 0 && t < W_DIM)
                   ? *(const u64*)(ld_base + (long long)i * C_DIM) : 0ull;
            } else {
                xv = *(const u64*)(ld_base + (long long)i * C_DIM);
            }
            xr[u & 7] = xv;

            // ---- stage 1: y1[p1], p1 = t0+i-4 ; x[p1-3+k] lives at ring (u-7+k)&7
            u64 a0 = mul2(xr[(u - 7) & 7], w1r[0]);
            u64 a1 = mul2(xr[(u - 6) & 7], w1r[1]);
            a0 = fma2(xr[(u - 5) & 7], w1r[2], a0);
            a1 = fma2(xr[(u - 4) & 7], w1r[3], a1);
            a0 = fma2(xr[(u - 3) & 7], w1r[4], a0);
            a1 = fma2(xr[(u - 2) & 7], w1r[5], a1);
            a0 = fma2(xr[(u - 1) & 7], w1r[6], a0);
            a1 = fma2(xr[(u - 0) & 7], w1r[7], a1);
            u64 y1v = relu2(add2(a0, a1));
            if (BOUNDARY) {
                const int p1 = t0 + i - 4;
                if (p1 < 0 || p1 >= W_DIM) y1v = 0ull;   // conv output outside row must be 0
            }
            y1r[u & 15] = y1v;

            // ---- stage 2: y2[p2], p2 = t0+i-11 ; y1[p2-7+2k] at ring (u-14+2k)&15
            u64 b0 = mul2(y1r[(u - 14) & 15], w2r[0]);
            u64 b1 = mul2(y1r[(u - 12) & 15], w2r[1]);
            b0 = fma2(y1r[(u - 10) & 15], w2r[2], b0);
            b1 = fma2(y1r[(u -  8) & 15], w2r[3], b1);
            b0 = fma2(y1r[(u -  6) & 15], w2r[4], b0);
            b1 = fma2(y1r[(u -  4) & 15], w2r[5], b1);
            b0 = fma2(y1r[(u -  2) & 15], w2r[6], b0);
            b1 = fma2(y1r[(u -  0) & 15], w2r[7], b1);
            u64 y2v = relu2(add2(b0, b1));
            if (BOUNDARY) {
                const int p2 = t0 + i - 11;
                if (p2 < 0 || p2 >= W_DIM) y2v = 0ull;
            }
            y2r[u & 31] = y2v;

            // ---- stage 3: y3[p3], p3 = t0+i-25 ; y2[p3-14+4k] at ring (u-28+4k)&31
            u64 c0 = mul2(y2r[(u - 28) & 31], w3r[0]);
            u64 c1 = mul2(y2r[(u - 24) & 31], w3r[1]);
            c0 = fma2(y2r[(u - 20) & 31], w3r[2], c0);
            c1 = fma2(y2r[(u - 16) & 31], w3r[3], c1);
            c0 = fma2(y2r[(u - 12) & 31], w3r[4], c0);
            c1 = fma2(y2r[(u -  8) & 31], w3r[5], c1);
            c0 = fma2(y2r[(u -  4) & 31], w3r[6], c0);
            c1 = fma2(y2r[(u -  0) & 31], w3r[7], c1);
            const u64 y3v = relu2(add2(c0, c1));

            // store for p3 in [s0, s0+L) <=> i in [49, 49+L)
            if (i >= 49 && i < 49 + L_SEG) {
                *(u64*)(st_base + (long long)i * C_DIM) = y3v;
            }
        }
    }
}

extern "C" void kernel_launch(void* const* d_in, const int* in_sizes, int n_in,
                              void* d_out, int out_size)
{
    const float* x  = (const float*)d_in[0];
    const float* w1 = (const float*)d_in[1];
    const float* w2 = (const float*)d_in[2];
    const float* w3 = (const float*)d_in[3];
    float* out = (float*)d_out;

    (void)in_sizes; (void)n_in; (void)out_size;

    // interior segments: 336 rows * 14 segs = 4704 warps -> 1176 blocks of 128 thr
    conv_stack_kernel<false><<<(BH * (SEGS - 2)) / 4, 128>>>(x, w1, w2, w3, out);
    // boundary segments (seg 0 and seg 15): 672 warps -> 168 blocks
    conv_stack_kernel<true><<<(BH * 2) / 4, 128>>>(x, w1, w2, w3, out);
}

// round 2
// speedup vs baseline: 2.2440x; 2.2440x over previous
#include <cuda_runtime.h>

typedef unsigned long long u64;

// ---- packed f32x2 helpers (sm_103a) ----
__device__ __forceinline__ u64 pack2(float lo, float hi) {
    u64 d;
    asm("mov.b64 %0, {%1, %2};" : "=l"(d) : "r"(__float_as_uint(lo)), "r"(__float_as_uint(hi)));
    return d;
}
__device__ __forceinline__ void unpack2(u64 v, float& lo, float& hi) {
    unsigned a, b;
    asm("mov.b64 {%0, %1}, %2;" : "=r"(a), "=r"(b) : "l"(v));
    lo = __uint_as_float(a); hi = __uint_as_float(b);
}
__device__ __forceinline__ u64 fma2(u64 a, u64 b, u64 c) {
    u64 d;
    asm("fma.rn.f32x2 %0, %1, %2, %3;" : "=l"(d) : "l"(a), "l"(b), "l"(c));
    return d;
}
__device__ __forceinline__ u64 mul2(u64 a, u64 b) {
    u64 d;
    asm("mul.rn.f32x2 %0, %1, %2;" : "=l"(d) : "l"(a), "l"(b));
    return d;
}
__device__ __forceinline__ u64 add2(u64 a, u64 b) {
    u64 d;
    asm("add.rn.f32x2 %0, %1, %2;" : "=l"(d) : "l"(a), "l"(b));
    return d;
}
__device__ __forceinline__ u64 relu2(u64 v) {
    float lo, hi; unpack2(v, lo, hi);          // free in SASS (reg pair)
    lo = fmaxf(lo, 0.0f); hi = fmaxf(hi, 0.0f);
    return pack2(lo, hi);
}

// ---- problem constants ----
constexpr int W_DIM = 4096;
constexpr int C_DIM = 64;
constexpr int L_SEG = 256;            // outputs per warp
constexpr int T_STEPS = 320;          // 305 needed (L+49), padded to mult of 32
constexpr int SEGS = W_DIM / L_SEG;   // 16
constexpr int BH = 16 * 21;           // 336 (B*H rows)
constexpr int PF = 8;                 // x prefetch distance (steps)

// Cross-correlation, zero pad. pad_lo: d=1 -> 3, d=2 -> 7, d=4 -> 14.
// y1[w] = relu(sum_k x [w- 3+  k] * w1[k])
// y2[w] = relu(sum_k y1[w- 7+ 2k] * w2[k])   (y1 := 0 outside [0,W))
// y3[w] = relu(sum_k y2[w-14+ 4k] * w3[k])   (y2 := 0 outside [0,W))
//
// Per-warp streaming pipeline, lane = 2 packed channels (f32x2):
//   x value for position index j (t = t0 + j) lives at ring slot j & 15.
//   At step i: LOAD position i+PF into slot (i+PF)&15 (8-step prefetch),
//   compute y1[t0+i-4] (x slots i-7..i), y2[t0+i-11], y3[t0+i-25].
//   Ring sizes 16/16/32 divide 32 => all indices static in the unrolled body.

template<bool BOUNDARY>
__device__ __forceinline__ void run_seg(
    const float* __restrict__ x,
    const u64* w1r, const u64* w2r, const u64* w3r,
    float* __restrict__ out,
    int bh, int seg, int lane)
{
    const int s0 = seg * L_SEG;
    const int t0 = s0 - 24;

    const float* ld_base = x   + ((long long)bh * W_DIM + t0) * C_DIM + 2 * lane;
    float*       st_base = out + ((long long)bh * W_DIM + (s0 - 49)) * C_DIM + 2 * lane;

    u64 xr[16], y1r[16], y2r[32];
    #pragma unroll
    for (int j = 0; j < 16; ++j) xr[j]  = 0ull;
    #pragma unroll
    for (int j = 0; j < 16; ++j) y1r[j] = 0ull;
    #pragma unroll
    for (int j = 0; j < 32; ++j) y2r[j] = 0ull;

    // warmup: preload positions 0..PF-1 into slots 0..PF-1
    #pragma unroll
    for (int j = 0; j < PF; ++j) {
        if (BOUNDARY) {
            const int t = t0 + j;
            xr[j] = (t >= 0 && t < W_DIM)
                  ? *(const u64*)(ld_base + (long long)j * C_DIM) : 0ull;
        } else {
            xr[j] = *(const u64*)(ld_base + (long long)j * C_DIM);
        }
    }

    for (int ib = 0; ib < T_STEPS; ib += 32) {
        #pragma unroll
        for (int u = 0; u < 32; ++u) {
            const int i = ib + u;

            // ---- prefetch x position i+PF into slot (u+PF)&15
            u64 xv;
            if (BOUNDARY) {
                const int t = t0 + i + PF;
                xv = (t >= 0 && t < W_DIM)
                   ? *(const u64*)(ld_base + (long long)(i + PF) * C_DIM) : 0ull;
            } else {
                xv = *(const u64*)(ld_base + (long long)(i + PF) * C_DIM);
            }
            xr[(u + PF) & 15] = xv;

            // ---- stage 1: y1[p1], p1 = t0+i-4 ; x[p1-3+k] at slot (u-7+k)&15
            u64 a0 = mul2(xr[(u - 7) & 15], w1r[0]);
            u64 a1 = mul2(xr[(u - 6) & 15], w1r[1]);
            a0 = fma2(xr[(u - 5) & 15], w1r[2], a0);
            a1 = fma2(xr[(u - 4) & 15], w1r[3], a1);
            a0 = fma2(xr[(u - 3) & 15], w1r[4], a0);
            a1 = fma2(xr[(u - 2) & 15], w1r[5], a1);
            a0 = fma2(xr[(u - 1) & 15], w1r[6], a0);
            a1 = fma2(xr[(u - 0) & 15], w1r[7], a1);
            u64 y1v = relu2(add2(a0, a1));
            if (BOUNDARY) {
                const int p1 = t0 + i - 4;
                if (p1 < 0 || p1 >= W_DIM) y1v = 0ull;   // conv output outside row is 0
            }
            y1r[u & 15] = y1v;

            // ---- stage 2: y2[p2], p2 = t0+i-11 ; y1 at slots (u-14+2k)&15
            u64 b0 = mul2(y1r[(u - 14) & 15], w2r[0]);
            u64 b1 = mul2(y1r[(u - 12) & 15], w2r[1]);
            b0 = fma2(y1r[(u - 10) & 15], w2r[2], b0);
            b1 = fma2(y1r[(u -  8) & 15], w2r[3], b1);
            b0 = fma2(y1r[(u -  6) & 15], w2r[4], b0);
            b1 = fma2(y1r[(u -  4) & 15], w2r[5], b1);
            b0 = fma2(y1r[(u -  2) & 15], w2r[6], b0);
            b1 = fma2(y1r[(u -  0) & 15], w2r[7], b1);
            u64 y2v = relu2(add2(b0, b1));
            if (BOUNDARY) {
                const int p2 = t0 + i - 11;
                if (p2 < 0 || p2 >= W_DIM) y2v = 0ull;
            }
            y2r[u & 31] = y2v;

            // ---- stage 3: y3[p3], p3 = t0+i-25 ; y2 at slots (u-28+4k)&31
            u64 c0 = mul2(y2r[(u - 28) & 31], w3r[0]);
            u64 c1 = mul2(y2r[(u - 24) & 31], w3r[1]);
            c0 = fma2(y2r[(u - 20) & 31], w3r[2], c0);
            c1 = fma2(y2r[(u - 16) & 31], w3r[3], c1);
            c0 = fma2(y2r[(u - 12) & 31], w3r[4], c0);
            c1 = fma2(y2r[(u -  8) & 31], w3r[5], c1);
            c0 = fma2(y2r[(u -  4) & 31], w3r[6], c0);
            c1 = fma2(y2r[(u -  0) & 31], w3r[7], c1);
            const u64 y3v = relu2(add2(c0, c1));

            // store for p3 in [s0, s0+L) <=> i in [49, 49+L)
            if (i >= 49 && i < 49 + L_SEG) {
                *(u64*)(st_base + (long long)i * C_DIM) = y3v;
            }
        }
    }
}

__global__ void __launch_bounds__(128)
conv_stack_kernel(const float* __restrict__ x,
                  const float* __restrict__ w1,
                  const float* __restrict__ w2,
                  const float* __restrict__ w3,
                  float* __restrict__ out)
{
    const int warp = blockIdx.x * 4 + (threadIdx.x >> 5);
    const int lane = threadIdx.x & 31;

    const int bh  = warp >> 4;        // warp / 16
    const int seg = warp & 15;        // warp % 16

    // per-channel-pair weights (8 taps each), contiguous float2 at k*64 + 2*lane
    u64 w1r[8], w2r[8], w3r[8];
    #pragma unroll
    for (int k = 0; k < 8; ++k) {
        w1r[k] = *(const u64*)(w1 + k * C_DIM + 2 * lane);
        w2r[k] = *(const u64*)(w2 + k * C_DIM + 2 * lane);
        w3r[k] = *(const u64*)(w3 + k * C_DIM + 2 * lane);
    }

    if (seg == 0 || seg == SEGS - 1) {
        run_seg<true >(x, w1r, w2r, w3r, out, bh, seg, lane);
    } else {
        run_seg<false>(x, w1r, w2r, w3r, out, bh, seg, lane);
    }
}

extern "C" void kernel_launch(void* const* d_in, const int* in_sizes, int n_in,
                              void* d_out, int out_size)
{
    const float* x  = (const float*)d_in[0];
    const float* w1 = (const float*)d_in[1];
    const float* w2 = (const float*)d_in[2];
    const float* w3 = (const float*)d_in[3];
    float* out = (float*)d_out;

    (void)in_sizes; (void)n_in; (void)out_size;

    // 336 rows * 16 segs = 5376 warps -> 1344 blocks of 128 threads, one launch
    conv_stack_kernel<<<(BH * SEGS) / 4, 128>>>(x, w1, w2, w3, out);
}